// round 5
// baseline (speedup 1.0000x reference)
#include <cuda_runtime.h>
#include <cuda_bf16.h>

// Problem constants
#define M_ROWS   4096          // b*NT*2*NO = 16*8*32
#define K_VIS    2048
#define FEAT     512
#define BT       128           // b*NT
#define NO       16
#define TGT      24
#define N_EDGE   (BT * NO * NO)        // 32768
#define OUT_LOGITS (N_EDGE * TGT)      // 786432

// Scratch (device globals; referenced ONLY in device code)
__device__ float g_h1[M_ROWS * FEAT];
__device__ float g_Ws[FEAT * TGT];     // wf @ wr_top
__device__ float g_Wo[FEAT * TGT];     // wf @ wr_bot
__device__ float g_W2s[FEAT * TGT];    // w2 @ Ws
__device__ float g_W2o[FEAT * TGT];    // w2 @ Wo
__device__ float g_bs[TGT];            // bf @ wr_top
__device__ float g_bo[TGT];            // bf @ wr_bot + br
__device__ float g_bs2[TGT];           // b2 @ Ws + bs
__device__ float g_bo2[TGT];           // b2 @ Wo + bo
__device__ float g_sout[BT * NO * TGT];
__device__ float g_oout[BT * NO * TGT];
__device__ float g_p1[128];
__device__ float g_p2[128];
__device__ int   g_tgt_is64;

typedef unsigned long long ull;

// ---------------------------------------------------------------------------
// Packed fp32x2 helpers (second FP32 datapath on sm_103a only via PTX f32x2)
// ---------------------------------------------------------------------------
__device__ __forceinline__ void ffma2(ull& d, ull a, ull b) {
    asm("fma.rn.f32x2 %0, %1, %2, %0;" : "+l"(d) : "l"(a), "l"(b));
}
__device__ __forceinline__ void unpack2(float& lo, float& hi, ull v) {
    asm("mov.b64 {%0, %1}, %2;" : "=f"(lo), "=f"(hi) : "l"(v));
}

// ---------------------------------------------------------------------------
// GEMM1: g_h1 = relu(src @ w1 + b1).  M=4096, N=512, K=2048.
// BM=64, BN=128, BK=16, 128 threads, 8x8 per-thread microtile, FFMA2,
// B pre-duplicated {v,v} in smem (no broadcast movs), double buffer,
// one __syncthreads per BK tile.
// ---------------------------------------------------------------------------
#define BM 64
#define BN 128
#define BK 16
#define ASTR 68     // As row stride (floats): 68*4 bytes, 16B-aligned

__device__ __forceinline__ void stdup(float* p, float4 v) {
    *reinterpret_cast<float4*>(p)     = make_float4(v.x, v.x, v.y, v.y);
    *reinterpret_cast<float4*>(p + 4) = make_float4(v.z, v.z, v.w, v.w);
}

__global__ __launch_bounds__(128, 2) void sgemm_relu(
    const float* __restrict__ A, const float* __restrict__ B,
    const float* __restrict__ bias)
{
    const int M = M_ROWS, N = FEAT, K = K_VIS;
    __shared__ float As[2][BK][ASTR];     // transposed: As[k][m]
    __shared__ float Bs[2][BK][2 * BN];   // duplicated pairs: col j -> [2j],[2j+1]

    const int tid = threadIdx.x;
    const int bm = blockIdx.y * BM;
    const int bn = blockIdx.x * BN;
    const int ty = tid >> 4;      // 0..7  -> rows ty*8
    const int tx = tid & 15;      // 0..15 -> cols tx*8

    // A tile: 64x16 floats; thread covers row tid>>1, cols (tid&1)*8 .. +7
    const int aRow = tid >> 1;
    const int aCol = (tid & 1) * 8;
    const float* Ap = A + (size_t)(bm + aRow) * K + aCol;
    // B tile: 16x128 floats; thread covers row tid>>3, 16 floats at (tid&7)*16
    const int bRow = tid >> 3;
    const int bColf = (tid & 7) * 16;
    const float* Bp = B + (size_t)bRow * N + bn + bColf;

    ull acc[4][8];
#pragma unroll
    for (int i = 0; i < 4; i++)
#pragma unroll
        for (int j = 0; j < 8; j++) acc[i][j] = 0ull;

    // Prologue: tile 0 -> buffer 0
    float4 a0 = *reinterpret_cast<const float4*>(Ap);
    float4 a1 = *reinterpret_cast<const float4*>(Ap + 4);
    float4 b0 = *reinterpret_cast<const float4*>(Bp);
    float4 b1 = *reinterpret_cast<const float4*>(Bp + 4);
    float4 b2 = *reinterpret_cast<const float4*>(Bp + 8);
    float4 b3 = *reinterpret_cast<const float4*>(Bp + 12);
    {
        As[0][aCol + 0][aRow] = a0.x; As[0][aCol + 1][aRow] = a0.y;
        As[0][aCol + 2][aRow] = a0.z; As[0][aCol + 3][aRow] = a0.w;
        As[0][aCol + 4][aRow] = a1.x; As[0][aCol + 5][aRow] = a1.y;
        As[0][aCol + 6][aRow] = a1.z; As[0][aCol + 7][aRow] = a1.w;
        float* bp0 = &Bs[0][bRow][2 * bColf];
        stdup(bp0,      b0);
        stdup(bp0 + 8,  b1);
        stdup(bp0 + 16, b2);
        stdup(bp0 + 24, b3);
    }
    __syncthreads();

    const int nTiles = K / BK;     // 128
    for (int t = 0; t < nTiles; t++) {
        const int cur = t & 1;
        const bool more = (t + 1 < nTiles);
        if (more) {
            Ap += BK;
            a0 = *reinterpret_cast<const float4*>(Ap);
            a1 = *reinterpret_cast<const float4*>(Ap + 4);
            Bp += (size_t)BK * N;
            b0 = *reinterpret_cast<const float4*>(Bp);
            b1 = *reinterpret_cast<const float4*>(Bp + 4);
            b2 = *reinterpret_cast<const float4*>(Bp + 8);
            b3 = *reinterpret_cast<const float4*>(Bp + 12);
        }

#pragma unroll
        for (int k = 0; k < BK; k++) {
            const ulonglong2 a01 =
                *reinterpret_cast<const ulonglong2*>(&As[cur][k][ty * 8]);
            const ulonglong2 a23 =
                *reinterpret_cast<const ulonglong2*>(&As[cur][k][ty * 8 + 4]);
            const ulonglong2 bA =
                *reinterpret_cast<const ulonglong2*>(&Bs[cur][k][tx * 16]);
            const ulonglong2 bB =
                *reinterpret_cast<const ulonglong2*>(&Bs[cur][k][tx * 16 + 4]);
            const ulonglong2 bC =
                *reinterpret_cast<const ulonglong2*>(&Bs[cur][k][tx * 16 + 8]);
            const ulonglong2 bD =
                *reinterpret_cast<const ulonglong2*>(&Bs[cur][k][tx * 16 + 12]);
            ull ap[4] = {a01.x, a01.y, a23.x, a23.y};
            ull bp[8] = {bA.x, bA.y, bB.x, bB.y, bC.x, bC.y, bD.x, bD.y};
#pragma unroll
            for (int i = 0; i < 4; i++)
#pragma unroll
                for (int j = 0; j < 8; j++)
                    ffma2(acc[i][j], ap[i], bp[j]);
        }

        if (more) {
            const int nxt = cur ^ 1;
            As[nxt][aCol + 0][aRow] = a0.x; As[nxt][aCol + 1][aRow] = a0.y;
            As[nxt][aCol + 2][aRow] = a0.z; As[nxt][aCol + 3][aRow] = a0.w;
            As[nxt][aCol + 4][aRow] = a1.x; As[nxt][aCol + 5][aRow] = a1.y;
            As[nxt][aCol + 6][aRow] = a1.z; As[nxt][aCol + 7][aRow] = a1.w;
            float* bp0 = &Bs[nxt][bRow][2 * bColf];
            stdup(bp0,      b0);
            stdup(bp0 + 8,  b1);
            stdup(bp0 + 16, b2);
            stdup(bp0 + 24, b3);
            __syncthreads();
        }
    }

    // Epilogue: bias + ReLU, STG.128
    const float4 bi0 = *reinterpret_cast<const float4*>(&bias[bn + tx * 8]);
    const float4 bi1 = *reinterpret_cast<const float4*>(&bias[bn + tx * 8 + 4]);
#pragma unroll
    for (int i2 = 0; i2 < 4; i2++) {
        float lo[8], hi[8];
#pragma unroll
        for (int j = 0; j < 8; j++) unpack2(lo[j], hi[j], acc[i2][j]);
        const float bv[8] = {bi0.x, bi0.y, bi0.z, bi0.w, bi1.x, bi1.y, bi1.z, bi1.w};
#pragma unroll
        for (int j = 0; j < 8; j++) {
            lo[j] = fmaxf(lo[j] + bv[j], 0.0f);
            hi[j] = fmaxf(hi[j] + bv[j], 0.0f);
        }
        const int r0 = bm + ty * 8 + 2 * i2;
        float* c0 = g_h1 + (size_t)r0 * N + bn + tx * 8;
        float* c1 = g_h1 + (size_t)(r0 + 1) * N + bn + tx * 8;
        *reinterpret_cast<float4*>(c0)     = make_float4(lo[0], lo[1], lo[2], lo[3]);
        *reinterpret_cast<float4*>(c0 + 4) = make_float4(lo[4], lo[5], lo[6], lo[7]);
        *reinterpret_cast<float4*>(c1)     = make_float4(hi[0], hi[1], hi[2], hi[3]);
        *reinterpret_cast<float4*>(c1 + 4) = make_float4(hi[4], hi[5], hi[6], hi[7]);
    }
}

// ---------------------------------------------------------------------------
// Weight projection: Out[f][t] = sum_{f'} Win[f][f'] * P[f'][t]
// PHASE 0: Win=wf, P = wr + half*FEAT*TGT  -> g_Ws / g_Wo
// PHASE 1: Win=w2, P = g_Ws / g_Wo         -> g_W2s / g_W2o
// grid (64, 2): 8 rows per block, y = half. One warp per row.
// ---------------------------------------------------------------------------
template <int PHASE>
__global__ __launch_bounds__(256) void wproj_kernel(
    const float* __restrict__ Win, const float* __restrict__ P0)
{
    __shared__ float ws[FEAT * TGT];   // 48KB
    const int half = blockIdx.y;
    const float* P = (PHASE == 0) ? (P0 + (size_t)half * FEAT * TGT)
                                  : (half ? g_Wo : g_Ws);
    float* dst = (PHASE == 0) ? (half ? g_Wo : g_Ws)
                              : (half ? g_W2o : g_W2s);
    for (int i = threadIdx.x; i < FEAT * TGT; i += 256) ws[i] = P[i];
    __syncthreads();

    const int w = threadIdx.x >> 5;
    const int lane = threadIdx.x & 31;
    const int f = blockIdx.x * 8 + w;
    const float* wrow = Win + (size_t)f * FEAT;

    float v[16];
#pragma unroll
    for (int i = 0; i < 16; i++) v[i] = wrow[lane + 32 * i];

    float acc[TGT];
#pragma unroll
    for (int t = 0; t < TGT; t++) acc[t] = 0.0f;
#pragma unroll
    for (int i = 0; i < 16; i++) {
        const float* pr = &ws[(lane + 32 * i) * TGT];
#pragma unroll
        for (int t = 0; t < TGT; t++) acc[t] = fmaf(v[i], pr[t], acc[t]);
    }
#pragma unroll
    for (int t = 0; t < TGT; t++)
#pragma unroll
        for (int off = 16; off > 0; off >>= 1)
            acc[t] += __shfl_xor_sync(0xFFFFFFFFu, acc[t], off);
    if (lane < TGT) dst[f * TGT + lane] = acc[lane];
}

// ---------------------------------------------------------------------------
// Bias folds.
// bias1: g_bs[t] = bf @ wr_top[:,t];  g_bo[t] = bf @ wr_bot[:,t] + br[t]
// bias2: g_bs2[t] = b2 @ Ws[:,t] + bs[t];  g_bo2[t] = b2 @ Wo[:,t] + bo[t]
// grid(2) = half, 768 threads = 24 warps, one warp per t.
// ---------------------------------------------------------------------------
__global__ __launch_bounds__(768) void bias1_kernel(
    const float* __restrict__ bf, const float* __restrict__ wr,
    const float* __restrict__ br)
{
    const int half = blockIdx.x;
    const int t = threadIdx.x >> 5;
    const int lane = threadIdx.x & 31;
    float s = 0.0f;
#pragma unroll
    for (int i = 0; i < 16; i++) {
        const int f = lane + 32 * i;
        s = fmaf(bf[f], wr[(size_t)(half * FEAT + f) * TGT + t], s);
    }
#pragma unroll
    for (int off = 16; off > 0; off >>= 1)
        s += __shfl_xor_sync(0xFFFFFFFFu, s, off);
    if (lane == 0) {
        if (half == 0) g_bs[t] = s;
        else           g_bo[t] = s + br[t];
    }
}

__global__ __launch_bounds__(768) void bias2_kernel(const float* __restrict__ b2)
{
    const int half = blockIdx.x;
    const int t = threadIdx.x >> 5;
    const int lane = threadIdx.x & 31;
    const float* W = half ? g_Wo : g_Ws;
    float s = 0.0f;
#pragma unroll
    for (int i = 0; i < 16; i++) {
        const int f = lane + 32 * i;
        s = fmaf(b2[f], W[(size_t)f * TGT + t], s);
    }
#pragma unroll
    for (int off = 16; off > 0; off >>= 1)
        s += __shfl_xor_sync(0xFFFFFFFFu, s, off);
    if (lane == 0) {
        if (half == 0) g_bs2[t] = s + g_bs[t];
        else           g_bo2[t] = s + g_bo[t];
    }
}

// ---------------------------------------------------------------------------
// Rel projection: row r of g_h1 (4096 rows x 512).
// n = r&31: n<NO -> subject (W2s, bs2), else object (W2o, bo2). 24 outputs.
// One warp per row, 8 rows/block; weight staged in smem (48KB).
// ---------------------------------------------------------------------------
__global__ __launch_bounds__(256) void rel_small_kernel()
{
    __shared__ float ws[FEAT * TGT];
    const int base = blockIdx.x * 8;
    const bool subj = ((base & 31) < NO);
    const float* wsel = subj ? g_W2s : g_W2o;
    for (int i = threadIdx.x; i < FEAT * TGT; i += 256) ws[i] = wsel[i];
    __syncthreads();

    const int w = threadIdx.x >> 5;
    const int lane = threadIdx.x & 31;
    const int r = base + w;
    const float* nr = g_h1 + (size_t)r * FEAT;

    float v[16];
#pragma unroll
    for (int i = 0; i < 16; i++) v[i] = nr[lane + 32 * i];

    float acc[TGT];
#pragma unroll
    for (int t = 0; t < TGT; t++) acc[t] = 0.0f;
#pragma unroll
    for (int i = 0; i < 16; i++) {
        const float* wrow = &ws[(lane + 32 * i) * TGT];
#pragma unroll
        for (int t = 0; t < TGT; t++) acc[t] = fmaf(v[i], wrow[t], acc[t]);
    }
#pragma unroll
    for (int t = 0; t < TGT; t++)
#pragma unroll
        for (int off = 16; off > 0; off >>= 1)
            acc[t] += __shfl_xor_sync(0xFFFFFFFFu, acc[t], off);

    const int bt = r >> 5;
    const int n = r & 31;
    float* dst = subj ? (g_sout + (size_t)(bt * NO + n) * TGT)
                      : (g_oout + (size_t)(bt * NO + (n - NO)) * TGT);
    if (lane < TGT) dst[lane] = acc[lane] + (subj ? g_bs2[lane] : g_bo2[lane]);
}

// ---------------------------------------------------------------------------
// Edge combine: out[bt, i*NO+j, t] = sout[bt,i,t] + oout[bt,j,t]
// (all biases pre-folded)
// ---------------------------------------------------------------------------
__global__ __launch_bounds__(256) void combine_kernel(float* __restrict__ out)
{
    const int idx = blockIdx.x * blockDim.x + threadIdx.x;
    if (idx >= OUT_LOGITS) return;
    const int t = idx % TGT;
    const int e = (idx / TGT) & 255;
    const int bt = idx / (TGT * NO * NO);
    const int i = e >> 4;
    const int j = e & 15;
    out[idx] = g_sout[(size_t)(bt * NO + i) * TGT + t]
             + g_oout[(size_t)(bt * NO + j) * TGT + t];
}

// ---------------------------------------------------------------------------
// Target dtype detection: int64 vs int32.
// ---------------------------------------------------------------------------
__global__ void detect_tgt_kernel(const int* __restrict__ tgt32)
{
    int allzero = 1;
    for (int i = 1; i < 128; i += 2)
        if (tgt32[i] != 0) { allzero = 0; break; }
    g_tgt_is64 = allzero;
}

// ---------------------------------------------------------------------------
// Loss: per-row weighted NLL, deterministic two-stage reduction.
// ---------------------------------------------------------------------------
__global__ __launch_bounds__(256) void loss_part_kernel(
    const float* __restrict__ out, const int* __restrict__ tgt32,
    float* __restrict__ tgtf)
{
    const int r = blockIdx.x * blockDim.x + threadIdx.x;
    const float* row = out + (size_t)r * TGT;
    float m = row[0];
#pragma unroll
    for (int t = 1; t < TGT; t++) m = fmaxf(m, row[t]);
    float s = 0.0f;
#pragma unroll
    for (int t = 0; t < TGT; t++) s += expf(row[t] - m);
    const int tg = g_tgt_is64 ? tgt32[2 * r] : tgt32[r];
    const float nll = logf(s) + m - row[tg];
    const float w = (tg == 0) ? 1.0f : 100.0f;
    tgtf[r] = (float)tg;

    __shared__ float sh1[256], sh2[256];
    sh1[threadIdx.x] = w * nll;
    sh2[threadIdx.x] = w;
    __syncthreads();
    for (int off = 128; off > 0; off >>= 1) {
        if (threadIdx.x < off) {
            sh1[threadIdx.x] += sh1[threadIdx.x + off];
            sh2[threadIdx.x] += sh2[threadIdx.x + off];
        }
        __syncthreads();
    }
    if (threadIdx.x == 0) { g_p1[blockIdx.x] = sh1[0]; g_p2[blockIdx.x] = sh2[0]; }
}

__global__ __launch_bounds__(128) void loss_final_kernel(float* __restrict__ loss)
{
    __shared__ float sh1[128], sh2[128];
    sh1[threadIdx.x] = g_p1[threadIdx.x];
    sh2[threadIdx.x] = g_p2[threadIdx.x];
    __syncthreads();
    for (int off = 64; off > 0; off >>= 1) {
        if (threadIdx.x < off) {
            sh1[threadIdx.x] += sh1[threadIdx.x + off];
            sh2[threadIdx.x] += sh2[threadIdx.x + off];
        }
        __syncthreads();
    }
    if (threadIdx.x == 0) loss[0] = sh1[0] / sh2[0];
}

// ---------------------------------------------------------------------------
extern "C" void kernel_launch(void* const* d_in, const int* in_sizes, int n_in,
                              void* d_out, int out_size)
{
    const float* src   = (const float*)d_in[0];
    const int*   tgt32 = (const int*)d_in[1];
    const float* w1 = (const float*)d_in[2];
    const float* b1 = (const float*)d_in[3];
    const float* w2 = (const float*)d_in[4];
    const float* b2 = (const float*)d_in[5];
    const float* wf = (const float*)d_in[6];
    const float* bf = (const float*)d_in[7];
    const float* wr = (const float*)d_in[8];
    const float* br = (const float*)d_in[9];
    float* out = (float*)d_out;

    detect_tgt_kernel<<<1, 1>>>(tgt32);
    // Precompute collapsed rel weights (w2 @ wf @ wr halves) + folded biases
    wproj_kernel<0><<<dim3(64, 2), 256>>>(wf, wr);
    bias1_kernel<<<2, 768>>>(bf, wr, br);
    wproj_kernel<1><<<dim3(64, 2), 256>>>(w2, nullptr);
    bias2_kernel<<<2, 768>>>(b2);
    // The only big GEMM: g_h1 = relu(src @ w1 + b1)
    sgemm_relu<<<dim3(FEAT / BN, M_ROWS / BM), 128>>>(src, w1, b1);
    // Per-node 24-dim projections
    rel_small_kernel<<<M_ROWS / 8, 256>>>();
    // edge logits -> d_out[0 : 786432]
    combine_kernel<<<(OUT_LOGITS + 255) / 256, 256>>>(out);
    // loss partials + tgt floats -> d_out[786432 : 819200]
    loss_part_kernel<<<128, 256>>>(out, tgt32, out + OUT_LOGITS);
    // loss scalar -> d_out[819200]
    loss_final_kernel<<<1, 128>>>(out + OUT_LOGITS + N_EDGE);
}

// round 6
// speedup vs baseline: 2.8338x; 2.8338x over previous
#include <cuda_runtime.h>
#include <cuda_bf16.h>

// Problem constants
#define M_ROWS   4096          // b*NT*2*NO = 16*8*32
#define K_VIS    2048
#define FEAT     512
#define BT       128           // b*NT
#define NO       16
#define TGT      24
#define N_EDGE   (BT * NO * NO)        // 32768
#define OUT_LOGITS (N_EDGE * TGT)      // 786432

// Scratch (device globals; referenced ONLY in device code)
__device__ float g_h1[M_ROWS * FEAT];
__device__ float g_Ws[FEAT * TGT];     // wf @ wr_top
__device__ float g_Wo[FEAT * TGT];     // wf @ wr_bot
__device__ float g_W2s[FEAT * TGT];    // w2 @ Ws
__device__ float g_W2o[FEAT * TGT];    // w2 @ Wo
__device__ float g_bs[TGT];            // bf @ wr_top
__device__ float g_bo[TGT];            // bf @ wr_bot + br
__device__ float g_bs2[TGT];           // b2 @ Ws + bs
__device__ float g_bo2[TGT];           // b2 @ Wo + bo
__device__ float g_sout[BT * NO * TGT];
__device__ float g_oout[BT * NO * TGT];
__device__ float g_p1[128];
__device__ float g_p2[128];
__device__ int   g_tgt_is64;

typedef unsigned long long ull;

// ---------------------------------------------------------------------------
// Packed fp32x2 helpers (second FP32 datapath on sm_103a only via PTX f32x2)
// ---------------------------------------------------------------------------
__device__ __forceinline__ void ffma2(ull& d, ull a, ull b) {
    asm("fma.rn.f32x2 %0, %1, %2, %0;" : "+l"(d) : "l"(a), "l"(b));
}
__device__ __forceinline__ ull bcast2(float v) {
    ull r;
    asm("mov.b64 %0, {%1, %1};" : "=l"(r) : "f"(v));
    return r;
}
__device__ __forceinline__ void unpack2(float& lo, float& hi, ull v) {
    asm("mov.b64 {%0, %1}, %2;" : "=f"(lo), "=f"(hi) : "l"(v));
}

// ---------------------------------------------------------------------------
// GEMM1 (R4-proven structure): g_h1 = relu(src @ w1 + b1).
// BM=128, BN=64, BK=8, 256 threads, 8(M)x4(N) microtile, FFMA2 with
// M-packed accumulators. Double-buffered smem, one sync per tile.
// ---------------------------------------------------------------------------
#define BM 128
#define BN 64
#define BK 8
#define AS_STRIDE 132

__global__ __launch_bounds__(256) void sgemm_relu(
    const float* __restrict__ A, const float* __restrict__ B,
    const float* __restrict__ bias, int M, int N, int K)
{
    float* __restrict__ C = g_h1;

    __shared__ float As[2][BK][AS_STRIDE];   // transposed: As[k][m]
    __shared__ float Bs[2][BK][BN];

    const int tid = threadIdx.x;
    const int bm = blockIdx.y * BM;
    const int bn = blockIdx.x * BN;

    const int ty = tid >> 4;        // 0..15 -> rows ty*8
    const int tx = tid & 15;        // 0..15 -> cols tx*4

    const int aRow = tid >> 1;          // 0..127
    const int aCol = (tid & 1) * 4;     // 0 or 4
    const int bRow = tid >> 4;          // only <8 used via tid<128
    const int bCol = (tid & 15) * 4;

    const float* Ap = A + (size_t)(bm + aRow) * K + aCol;
    const float* Bp = B + (size_t)bRow * N + bn + bCol;
    const bool bAct = (tid < 128);

    ull acc[4][4];
#pragma unroll
    for (int i = 0; i < 4; i++)
#pragma unroll
        for (int j = 0; j < 4; j++) acc[i][j] = 0ull;

    const int nTiles = K / BK;

    float4 aReg = *reinterpret_cast<const float4*>(Ap);
    float4 bReg = bAct ? *reinterpret_cast<const float4*>(Bp)
                       : make_float4(0.f, 0.f, 0.f, 0.f);
    As[0][aCol + 0][aRow] = aReg.x;
    As[0][aCol + 1][aRow] = aReg.y;
    As[0][aCol + 2][aRow] = aReg.z;
    As[0][aCol + 3][aRow] = aReg.w;
    if (bAct) *reinterpret_cast<float4*>(&Bs[0][bRow][bCol]) = bReg;
    __syncthreads();

    for (int t = 0; t < nTiles; t++) {
        const int cur = t & 1;
        const bool more = (t + 1 < nTiles);
        if (more) {
            Ap += BK;
            aReg = *reinterpret_cast<const float4*>(Ap);
            if (bAct) {
                Bp += (size_t)BK * N;
                bReg = *reinterpret_cast<const float4*>(Bp);
            }
        }

#pragma unroll
        for (int k = 0; k < BK; k++) {
            const ulonglong2 a01 =
                *reinterpret_cast<const ulonglong2*>(&As[cur][k][ty * 8]);
            const ulonglong2 a23 =
                *reinterpret_cast<const ulonglong2*>(&As[cur][k][ty * 8 + 4]);
            ull ap[4] = {a01.x, a01.y, a23.x, a23.y};

            const float4 b4 =
                *reinterpret_cast<const float4*>(&Bs[cur][k][tx * 4]);
            ull bp[4] = {bcast2(b4.x), bcast2(b4.y), bcast2(b4.z), bcast2(b4.w)};
#pragma unroll
            for (int i = 0; i < 4; i++)
#pragma unroll
                for (int j = 0; j < 4; j++)
                    ffma2(acc[i][j], ap[i], bp[j]);
        }

        if (more) {
            const int nxt = cur ^ 1;
            As[nxt][aCol + 0][aRow] = aReg.x;
            As[nxt][aCol + 1][aRow] = aReg.y;
            As[nxt][aCol + 2][aRow] = aReg.z;
            As[nxt][aCol + 3][aRow] = aReg.w;
            if (bAct) *reinterpret_cast<float4*>(&Bs[nxt][bRow][bCol]) = bReg;
            __syncthreads();
        }
    }

    // Epilogue: bias + ReLU, STG.128 per row
    const float4 bi = *reinterpret_cast<const float4*>(&bias[bn + tx * 4]);
#pragma unroll
    for (int i2 = 0; i2 < 4; i2++) {
        float4 lo, hi;
        unpack2(lo.x, hi.x, acc[i2][0]);
        unpack2(lo.y, hi.y, acc[i2][1]);
        unpack2(lo.z, hi.z, acc[i2][2]);
        unpack2(lo.w, hi.w, acc[i2][3]);
        lo.x = fmaxf(lo.x + bi.x, 0.f); lo.y = fmaxf(lo.y + bi.y, 0.f);
        lo.z = fmaxf(lo.z + bi.z, 0.f); lo.w = fmaxf(lo.w + bi.w, 0.f);
        hi.x = fmaxf(hi.x + bi.x, 0.f); hi.y = fmaxf(hi.y + bi.y, 0.f);
        hi.z = fmaxf(hi.z + bi.z, 0.f); hi.w = fmaxf(hi.w + bi.w, 0.f);
        const int r0 = bm + ty * 8 + 2 * i2;
        *reinterpret_cast<float4*>(C + (size_t)r0 * N + bn + tx * 4) = lo;
        *reinterpret_cast<float4*>(C + (size_t)(r0 + 1) * N + bn + tx * 4) = hi;
    }
}

// ---------------------------------------------------------------------------
// Weight projection: Out[f][t] = sum_{f'} Win[f][f'] * P[f'][t]
// PHASE 0: Win=wf, P = wr + half*FEAT*TGT  -> g_Ws / g_Wo
// PHASE 1: Win=w2, P = g_Ws / g_Wo         -> g_W2s / g_W2o
// ---------------------------------------------------------------------------
template <int PHASE>
__global__ __launch_bounds__(256) void wproj_kernel(
    const float* __restrict__ Win, const float* __restrict__ P0)
{
    __shared__ float ws[FEAT * TGT];   // 48KB
    const int half = blockIdx.y;
    const float* P = (PHASE == 0) ? (P0 + (size_t)half * FEAT * TGT)
                                  : (half ? g_Wo : g_Ws);
    float* dst = (PHASE == 0) ? (half ? g_Wo : g_Ws)
                              : (half ? g_W2o : g_W2s);
    for (int i = threadIdx.x; i < FEAT * TGT; i += 256) ws[i] = P[i];
    __syncthreads();

    const int w = threadIdx.x >> 5;
    const int lane = threadIdx.x & 31;
    const int f = blockIdx.x * 8 + w;
    const float* wrow = Win + (size_t)f * FEAT;

    float v[16];
#pragma unroll
    for (int i = 0; i < 16; i++) v[i] = wrow[lane + 32 * i];

    float acc[TGT];
#pragma unroll
    for (int t = 0; t < TGT; t++) acc[t] = 0.0f;
#pragma unroll
    for (int i = 0; i < 16; i++) {
        const float* pr = &ws[(lane + 32 * i) * TGT];
#pragma unroll
        for (int t = 0; t < TGT; t++) acc[t] = fmaf(v[i], pr[t], acc[t]);
    }
#pragma unroll
    for (int t = 0; t < TGT; t++)
#pragma unroll
        for (int off = 16; off > 0; off >>= 1)
            acc[t] += __shfl_xor_sync(0xFFFFFFFFu, acc[t], off);
    if (lane < TGT) dst[f * TGT + lane] = acc[lane];
}

// ---------------------------------------------------------------------------
// Bias folds.
// ---------------------------------------------------------------------------
__global__ __launch_bounds__(768) void bias1_kernel(
    const float* __restrict__ bf, const float* __restrict__ wr,
    const float* __restrict__ br)
{
    const int half = blockIdx.x;
    const int t = threadIdx.x >> 5;
    const int lane = threadIdx.x & 31;
    float s = 0.0f;
#pragma unroll
    for (int i = 0; i < 16; i++) {
        const int f = lane + 32 * i;
        s = fmaf(bf[f], wr[(size_t)(half * FEAT + f) * TGT + t], s);
    }
#pragma unroll
    for (int off = 16; off > 0; off >>= 1)
        s += __shfl_xor_sync(0xFFFFFFFFu, s, off);
    if (lane == 0) {
        if (half == 0) g_bs[t] = s;
        else           g_bo[t] = s + br[t];
    }
}

__global__ __launch_bounds__(768) void bias2_kernel(const float* __restrict__ b2)
{
    const int half = blockIdx.x;
    const int t = threadIdx.x >> 5;
    const int lane = threadIdx.x & 31;
    const float* W = half ? g_Wo : g_Ws;
    float s = 0.0f;
#pragma unroll
    for (int i = 0; i < 16; i++) {
        const int f = lane + 32 * i;
        s = fmaf(b2[f], W[(size_t)f * TGT + t], s);
    }
#pragma unroll
    for (int off = 16; off > 0; off >>= 1)
        s += __shfl_xor_sync(0xFFFFFFFFu, s, off);
    if (lane == 0) {
        if (half == 0) g_bs2[t] = s + g_bs[t];
        else           g_bo2[t] = s + g_bo[t];
    }
}

// ---------------------------------------------------------------------------
// Rel projection on folded weights: row r of g_h1 (post-ReLU).
// n = r&31: n<NO -> subject (W2s, bs2), else object (W2o, bo2).
// ---------------------------------------------------------------------------
__global__ __launch_bounds__(256) void rel_small_kernel()
{
    __shared__ float ws[FEAT * TGT];
    const int base = blockIdx.x * 8;
    const bool subj = ((base & 31) < NO);
    const float* wsel = subj ? g_W2s : g_W2o;
    for (int i = threadIdx.x; i < FEAT * TGT; i += 256) ws[i] = wsel[i];
    __syncthreads();

    const int w = threadIdx.x >> 5;
    const int lane = threadIdx.x & 31;
    const int r = base + w;
    const float* nr = g_h1 + (size_t)r * FEAT;

    float v[16];
#pragma unroll
    for (int i = 0; i < 16; i++) v[i] = nr[lane + 32 * i];

    float acc[TGT];
#pragma unroll
    for (int t = 0; t < TGT; t++) acc[t] = 0.0f;
#pragma unroll
    for (int i = 0; i < 16; i++) {
        const float* wrow = &ws[(lane + 32 * i) * TGT];
#pragma unroll
        for (int t = 0; t < TGT; t++) acc[t] = fmaf(v[i], wrow[t], acc[t]);
    }
#pragma unroll
    for (int t = 0; t < TGT; t++)
#pragma unroll
        for (int off = 16; off > 0; off >>= 1)
            acc[t] += __shfl_xor_sync(0xFFFFFFFFu, acc[t], off);

    const int bt = r >> 5;
    const int n = r & 31;
    float* dst = subj ? (g_sout + (size_t)(bt * NO + n) * TGT)
                      : (g_oout + (size_t)(bt * NO + (n - NO)) * TGT);
    if (lane < TGT) dst[lane] = acc[lane] + (subj ? g_bs2[lane] : g_bo2[lane]);
}

// ---------------------------------------------------------------------------
// Edge combine: out[bt, i*NO+j, t] = sout[bt,i,t] + oout[bt,j,t]
// ---------------------------------------------------------------------------
__global__ __launch_bounds__(256) void combine_kernel(float* __restrict__ out)
{
    const int idx = blockIdx.x * blockDim.x + threadIdx.x;
    if (idx >= OUT_LOGITS) return;
    const int t = idx % TGT;
    const int e = (idx / TGT) & 255;
    const int bt = idx / (TGT * NO * NO);
    const int i = e >> 4;
    const int j = e & 15;
    out[idx] = g_sout[(size_t)(bt * NO + i) * TGT + t]
             + g_oout[(size_t)(bt * NO + j) * TGT + t];
}

// ---------------------------------------------------------------------------
// Target dtype detection: int64 vs int32.
// ---------------------------------------------------------------------------
__global__ void detect_tgt_kernel(const int* __restrict__ tgt32)
{
    int allzero = 1;
    for (int i = 1; i < 128; i += 2)
        if (tgt32[i] != 0) { allzero = 0; break; }
    g_tgt_is64 = allzero;
}

// ---------------------------------------------------------------------------
// Loss: per-row weighted NLL, deterministic two-stage reduction.
// ---------------------------------------------------------------------------
__global__ __launch_bounds__(256) void loss_part_kernel(
    const float* __restrict__ out, const int* __restrict__ tgt32,
    float* __restrict__ tgtf)
{
    const int r = blockIdx.x * blockDim.x + threadIdx.x;
    const float* row = out + (size_t)r * TGT;
    float m = row[0];
#pragma unroll
    for (int t = 1; t < TGT; t++) m = fmaxf(m, row[t]);
    float s = 0.0f;
#pragma unroll
    for (int t = 0; t < TGT; t++) s += expf(row[t] - m);
    const int tg = g_tgt_is64 ? tgt32[2 * r] : tgt32[r];
    const float nll = logf(s) + m - row[tg];
    const float w = (tg == 0) ? 1.0f : 100.0f;
    tgtf[r] = (float)tg;

    __shared__ float sh1[256], sh2[256];
    sh1[threadIdx.x] = w * nll;
    sh2[threadIdx.x] = w;
    __syncthreads();
    for (int off = 128; off > 0; off >>= 1) {
        if (threadIdx.x < off) {
            sh1[threadIdx.x] += sh1[threadIdx.x + off];
            sh2[threadIdx.x] += sh2[threadIdx.x + off];
        }
        __syncthreads();
    }
    if (threadIdx.x == 0) { g_p1[blockIdx.x] = sh1[0]; g_p2[blockIdx.x] = sh2[0]; }
}

__global__ __launch_bounds__(128) void loss_final_kernel(float* __restrict__ loss)
{
    __shared__ float sh1[128], sh2[128];
    sh1[threadIdx.x] = g_p1[threadIdx.x];
    sh2[threadIdx.x] = g_p2[threadIdx.x];
    __syncthreads();
    for (int off = 64; off > 0; off >>= 1) {
        if (threadIdx.x < off) {
            sh1[threadIdx.x] += sh1[threadIdx.x + off];
            sh2[threadIdx.x] += sh2[threadIdx.x + off];
        }
        __syncthreads();
    }
    if (threadIdx.x == 0) loss[0] = sh1[0] / sh2[0];
}

// ---------------------------------------------------------------------------
extern "C" void kernel_launch(void* const* d_in, const int* in_sizes, int n_in,
                              void* d_out, int out_size)
{
    const float* src   = (const float*)d_in[0];
    const int*   tgt32 = (const int*)d_in[1];
    const float* w1 = (const float*)d_in[2];
    const float* b1 = (const float*)d_in[3];
    const float* w2 = (const float*)d_in[4];
    const float* b2 = (const float*)d_in[5];
    const float* wf = (const float*)d_in[6];
    const float* bf = (const float*)d_in[7];
    const float* wr = (const float*)d_in[8];
    const float* br = (const float*)d_in[9];
    float* out = (float*)d_out;

    detect_tgt_kernel<<<1, 1>>>(tgt32);
    // Precompute collapsed rel weights (w2 @ wf @ wr halves) + folded biases
    wproj_kernel<0><<<dim3(64, 2), 256>>>(wf, wr);
    bias1_kernel<<<2, 768>>>(bf, wr, br);
    wproj_kernel<1><<<dim3(64, 2), 256>>>(w2, nullptr);
    bias2_kernel<<<2, 768>>>(b2);
    // The only big GEMM (R4-proven layout): g_h1 = relu(src @ w1 + b1)
    sgemm_relu<<<dim3(FEAT / BN, M_ROWS / BM), 256>>>(src, w1, b1,
                                                      M_ROWS, FEAT, K_VIS);
    // Per-node 24-dim projections
    rel_small_kernel<<<M_ROWS / 8, 256>>>();
    // edge logits -> d_out[0 : 786432]
    combine_kernel<<<(OUT_LOGITS + 255) / 256, 256>>>(out);
    // loss partials + tgt floats -> d_out[786432 : 819200]
    loss_part_kernel<<<128, 256>>>(out, tgt32, out + OUT_LOGITS);
    // loss scalar -> d_out[819200]
    loss_final_kernel<<<1, 128>>>(out + OUT_LOGITS + N_EDGE);
}